// round 5
// baseline (speedup 1.0000x reference)
#include <cuda_runtime.h>
#include <cuda_bf16.h>
#include <math.h>
#include <stdint.h>

// Problem constants
#define B_  4
#define T_  2048
#define S_  2048
#define C_  512
#define H_  16
#define D_  32

#define NX  ((size_t)B_*T_*C_)   // 4194304
#define NW  ((size_t)C_*C_)      // 262144

// bf16 hi/lo scratch (device globals; no allocations allowed)
__device__ uint16_t g_xh[NX],  g_xl[NX];
__device__ uint16_t g_ch[NX],  g_cl[NX];
__device__ uint16_t g_wqh[NW], g_wql[NW];
__device__ uint16_t g_wkh[NW], g_wkl[NW];
__device__ uint16_t g_wvh[NW], g_wvl[NW];
__device__ uint16_t g_woh[NW], g_wol[NW];
__device__ uint16_t g_Qh[NX],  g_Ql[NX];   // [B,H,T,D] (pre-scaled)
__device__ uint16_t g_Kh[NX],  g_Kl[NX];   // [B,H,S,D]
__device__ uint16_t g_Vh[NX],  g_Vl[NX];   // [B,H,S,D]
__device__ uint16_t g_AOh[NX], g_AOl[NX];  // [B,T,C]

// ===========================================================================
// Helpers (compute_103-base-safe PTX)
// ===========================================================================
__device__ __forceinline__ uint32_t smem_u32(const void* p) {
    uint32_t a;
    asm("{ .reg .u64 t; cvta.to.shared.u64 t, %1; cvt.u32.u64 %0, t; }"
        : "=r"(a) : "l"(p));
    return a;
}
__device__ __forceinline__ void ldsm4(uint32_t addr, uint32_t& r0, uint32_t& r1,
                                      uint32_t& r2, uint32_t& r3) {
    asm volatile("ldmatrix.sync.aligned.m8n8.x4.shared.b16 {%0,%1,%2,%3}, [%4];"
                 : "=r"(r0), "=r"(r1), "=r"(r2), "=r"(r3) : "r"(addr));
}
__device__ __forceinline__ void ldsm4t(uint32_t addr, uint32_t& r0, uint32_t& r1,
                                       uint32_t& r2, uint32_t& r3) {
    asm volatile("ldmatrix.sync.aligned.m8n8.x4.trans.shared.b16 {%0,%1,%2,%3}, [%4];"
                 : "=r"(r0), "=r"(r1), "=r"(r2), "=r"(r3) : "r"(addr));
}
__device__ __forceinline__ void mmabf(float* d, const uint32_t* a,
                                      uint32_t b0, uint32_t b1) {
    asm volatile("mma.sync.aligned.m16n8k16.row.col.f32.bf16.bf16.f32 "
                 "{%0,%1,%2,%3}, {%4,%5,%6,%7}, {%8,%9}, {%0,%1,%2,%3};"
                 : "+f"(d[0]), "+f"(d[1]), "+f"(d[2]), "+f"(d[3])
                 : "r"(a[0]), "r"(a[1]), "r"(a[2]), "r"(a[3]),
                   "r"(b0), "r"(b1));
}
__device__ __forceinline__ uint32_t bfpack(float x0, float x1) {
    __nv_bfloat162 t = __floats2bfloat162_rn(x0, x1);
    return *reinterpret_cast<uint32_t*>(&t);
}
__device__ __forceinline__ void split2(float x0, float x1, uint32_t& hi, uint32_t& lo) {
    float h0 = __bfloat162float(__float2bfloat16(x0));
    float h1 = __bfloat162float(__float2bfloat16(x1));
    hi = bfpack(x0, x1);
    lo = bfpack(x0 - h0, x1 - h1);
}
__device__ __forceinline__ float ex2f(float x) {
    float y; asm("ex2.approx.ftz.f32 %0, %1;" : "=f"(y) : "f"(x)); return y;
}

// ===========================================================================
// Conversion prepass: fp32 -> (hi, lo) bf16 arrays, once per element.
// z: 0=x 1=ctx 2=Wq 3=Wk 4=Wv 5=Wo
// ===========================================================================
__global__ __launch_bounds__(256)
void conv_kernel(const float* __restrict__ x, const float* __restrict__ ctx,
                 const float* __restrict__ Wq, const float* __restrict__ Wk,
                 const float* __restrict__ Wv, const float* __restrict__ Wo)
{
    const int z = blockIdx.y;
    const float* src; uint16_t* dh; uint16_t* dl; size_t n;
    switch (z) {
        case 0:  src = x;   dh = g_xh;  dl = g_xl;  n = NX; break;
        case 1:  src = ctx; dh = g_ch;  dl = g_cl;  n = NX; break;
        case 2:  src = Wq;  dh = g_wqh; dl = g_wql; n = NW; break;
        case 3:  src = Wk;  dh = g_wkh; dl = g_wkl; n = NW; break;
        case 4:  src = Wv;  dh = g_wvh; dl = g_wvl; n = NW; break;
        default: src = Wo;  dh = g_woh; dl = g_wol; n = NW; break;
    }
    size_t id = (size_t)blockIdx.x * 256 + threadIdx.x;
    if (id * 4 >= n) return;
    float4 v = *(const float4*)(src + id * 4);
    uint32_t h0, l0, h1, l1;
    split2(v.x, v.y, h0, l0);
    split2(v.z, v.w, h1, l1);
    *(uint2*)(dh + id * 4) = make_uint2(h0, h1);
    *(uint2*)(dl + id * 4) = make_uint2(l0, l1);
}

// ===========================================================================
// GEMM core (bf16 hi/lo in): C = A(Mx512) @ W(512x512) + bias (then *outscale)
// CTA 128x64, 8 warps (4m x 2n), warp tile 32x32, K-chunk 32.
// MODE=1: write (hi,lo) bf16 into [B,H,T,D]; MODE=0: fp32 [M,512].
// ===========================================================================
#define GLDA 40   // halfword stride (32 + 8 pad)
#define GLDB 72   // halfword stride (64 + 8 pad)

template<int MODE>
__device__ __forceinline__
void gemm_body(const uint16_t* __restrict__ Ah, const uint16_t* __restrict__ Al,
               const uint16_t* __restrict__ Bh, const uint16_t* __restrict__ Bl,
               const float* __restrict__ bias, float* __restrict__ Cf,
               uint16_t* __restrict__ Ch, uint16_t* __restrict__ Cl,
               float outscale, int bm, int bn)
{
    __shared__ uint16_t sAh[128 * GLDA], sAl[128 * GLDA];
    __shared__ uint16_t sBh[32 * GLDB],  sBl[32 * GLDB];

    const int tid = threadIdx.x;
    const int lane = tid & 31, wid = tid >> 5;
    const int g = lane >> 3, r = lane & 7;
    const int tq = lane >> 2, tc = lane & 3;
    const int wm = wid >> 1, wn = wid & 1;

    float acc[2][4][4];
    #pragma unroll
    for (int i = 0; i < 2; i++)
        #pragma unroll
        for (int j = 0; j < 4; j++)
            #pragma unroll
            for (int k = 0; k < 4; k++) acc[i][j][k] = 0.f;

    // staging registers (bf16 x8 per uint4)
    uint4 rah[2], ral[2], rbh, rbl;
    {
        #pragma unroll
        for (int i = 0; i < 2; ++i) {
            int id = i * 256 + tid, row = id >> 2, c8 = (id & 3) * 8;
            rah[i] = *(const uint4*)(Ah + (size_t)(bm + row) * 512 + c8);
            ral[i] = *(const uint4*)(Al + (size_t)(bm + row) * 512 + c8);
        }
        int k = tid >> 3, n8 = (tid & 7) * 8;
        rbh = *(const uint4*)(Bh + (size_t)k * 512 + bn + n8);
        rbl = *(const uint4*)(Bl + (size_t)k * 512 + bn + n8);
    }

    const uint32_t bAh = smem_u32(sAh), bAl = smem_u32(sAl);
    const uint32_t bBh = smem_u32(sBh), bBl = smem_u32(sBl);

    for (int c = 0; c < 16; ++c) {
        #pragma unroll
        for (int i = 0; i < 2; ++i) {
            int id = i * 256 + tid, row = id >> 2, c8 = (id & 3) * 8;
            *(uint4*)&sAh[row * GLDA + c8] = rah[i];
            *(uint4*)&sAl[row * GLDA + c8] = ral[i];
        }
        {
            int k = tid >> 3, n8 = (tid & 7) * 8;
            *(uint4*)&sBh[k * GLDB + n8] = rbh;
            *(uint4*)&sBl[k * GLDB + n8] = rbl;
        }
        __syncthreads();

        if (c < 15) {
            #pragma unroll
            for (int i = 0; i < 2; ++i) {
                int id = i * 256 + tid, row = id >> 2, c8 = (id & 3) * 8;
                rah[i] = *(const uint4*)(Ah + (size_t)(bm + row) * 512 + (c + 1) * 32 + c8);
                ral[i] = *(const uint4*)(Al + (size_t)(bm + row) * 512 + (c + 1) * 32 + c8);
            }
            int k = tid >> 3, n8 = (tid & 7) * 8;
            rbh = *(const uint4*)(Bh + (size_t)((c + 1) * 32 + k) * 512 + bn + n8);
            rbl = *(const uint4*)(Bl + (size_t)((c + 1) * 32 + k) * 512 + bn + n8);
        }

        #pragma unroll
        for (int kb = 0; kb < 2; ++kb) {
            uint32_t ah[2][4], al[2][4];
            #pragma unroll
            for (int mf = 0; mf < 2; ++mf) {
                int row = wm * 32 + mf * 16 + (g & 1) * 8 + r;
                int hw  = kb * 16 + (g >> 1) * 8;
                uint32_t off = (uint32_t)(row * GLDA + hw) * 2;
                ldsm4(bAh + off, ah[mf][0], ah[mf][1], ah[mf][2], ah[mf][3]);
                ldsm4(bAl + off, al[mf][0], al[mf][1], al[mf][2], al[mf][3]);
            }
            #pragma unroll
            for (int nb = 0; nb < 2; ++nb) {
                int krow = kb * 16 + (g & 1) * 8 + r;
                int hw   = wn * 32 + nb * 16 + (g >> 1) * 8;
                uint32_t off = (uint32_t)(krow * GLDB + hw) * 2;
                uint32_t bh[4], bl[4];
                ldsm4t(bBh + off, bh[0], bh[1], bh[2], bh[3]);
                ldsm4t(bBl + off, bl[0], bl[1], bl[2], bl[3]);
                #pragma unroll
                for (int mf = 0; mf < 2; ++mf) {
                    #pragma unroll
                    for (int h2 = 0; h2 < 2; ++h2) {
                        float* d = acc[mf][nb * 2 + h2];
                        mmabf(d, ah[mf], bh[h2 * 2], bh[h2 * 2 + 1]);
                        mmabf(d, ah[mf], bl[h2 * 2], bl[h2 * 2 + 1]);
                        mmabf(d, al[mf], bh[h2 * 2], bh[h2 * 2 + 1]);
                    }
                }
            }
        }
        __syncthreads();
    }

    #pragma unroll
    for (int mf = 0; mf < 2; ++mf) {
        int row0 = bm + wm * 32 + mf * 16 + tq;
        #pragma unroll
        for (int nf = 0; nf < 4; ++nf) {
            int col = bn + wn * 32 + nf * 8 + tc * 2;
            float b0v = bias[col], b1v = bias[col + 1];
            float v00 = (acc[mf][nf][0] + b0v) * outscale;
            float v01 = (acc[mf][nf][1] + b1v) * outscale;
            float v10 = (acc[mf][nf][2] + b0v) * outscale;
            float v11 = (acc[mf][nf][3] + b1v) * outscale;
            if (MODE == 1) {
                int bb = row0 >> 11, t = row0 & 2047;
                int hh = col >> 5, d = col & 31;
                size_t i0 = (((size_t)(bb * H_ + hh)) * T_ + t) * D_ + d;
                size_t i1 = (((size_t)(bb * H_ + hh)) * T_ + t + 8) * D_ + d;
                uint32_t h, l;
                split2(v00, v01, h, l);
                *(uint32_t*)&Ch[i0] = h; *(uint32_t*)&Cl[i0] = l;
                split2(v10, v11, h, l);
                *(uint32_t*)&Ch[i1] = h; *(uint32_t*)&Cl[i1] = l;
            } else {
                *(float2*)&Cf[(size_t)row0 * 512 + col] = make_float2(v00, v01);
                *(float2*)&Cf[(size_t)(row0 + 8) * 512 + col] = make_float2(v10, v11);
            }
        }
    }
}

// Fused Q/K/V projection: blockIdx.z selects which GEMM.
__global__ __launch_bounds__(256)
void gemm_qkv_kernel(const float* __restrict__ bq, const float* __restrict__ bk,
                     const float* __restrict__ bv)
{
    const float SC = 0.17677669529663689f * 1.4426950408889634f; // scale*log2e
    const int z = blockIdx.z;
    const uint16_t *Ah, *Al, *Bh, *Bl;
    const float* bias;
    uint16_t *Ch, *Cl;
    float sc;
    if (z == 0) { Ah=g_xh; Al=g_xl; Bh=g_wqh; Bl=g_wql; bias=bq; Ch=g_Qh; Cl=g_Ql; sc=SC; }
    else if (z == 1) { Ah=g_ch; Al=g_cl; Bh=g_wkh; Bl=g_wkl; bias=bk; Ch=g_Kh; Cl=g_Kl; sc=1.f; }
    else { Ah=g_ch; Al=g_cl; Bh=g_wvh; Bl=g_wvl; bias=bv; Ch=g_Vh; Cl=g_Vl; sc=1.f; }
    gemm_body<1>(Ah, Al, Bh, Bl, bias, nullptr, Ch, Cl, sc,
                 blockIdx.y * 128, blockIdx.x * 64);
}

__global__ __launch_bounds__(256)
void gemm_out_kernel(const float* __restrict__ bo, float* __restrict__ out)
{
    gemm_body<0>(g_AOh, g_AOl, g_woh, g_wol, bo, out, nullptr, nullptr, 1.f,
                 blockIdx.y * 128, blockIdx.x * 64);
}

// ===========================================================================
// Flash attention on mma.sync (bf16 hi/lo operands direct from gmem).
// CTA: 128 query rows (8 warps x 16), S-tiles of 64. 3-term bf16 splits.
// ===========================================================================
#define ALD 40

__global__ __launch_bounds__(256)
void attn_mma_kernel()
{
    __shared__ uint16_t sm[10240];   // 20480 B

    const int tid = threadIdx.x, lane = tid & 31, wid = tid >> 5;
    const int g = lane >> 3, r = lane & 7;
    const int tq = lane >> 2, tc = lane & 3;
    const int bh = blockIdx.y, bidx = bh >> 4, hidx = bh & 15;
    const int t0 = blockIdx.x * 128;

    const uint32_t sb = smem_u32(sm);
    const uint32_t QHI = sb, QLO = sb + 10240;
    const uint32_t KHI = sb, KLO = sb + 5120, VHI = sb + 10240, VLO = sb + 15360;

    // ---- Q (pre-scaled) hi/lo -> smem -> registers ----
    #pragma unroll
    for (int i = 0; i < 2; ++i) {
        int id = i * 256 + tid, row = id >> 2, c8 = (id & 3) * 8;
        size_t gi = ((size_t)bh * T_ + t0 + row) * D_ + c8;
        *(uint4*)&sm[row * ALD + c8]        = *(const uint4*)(g_Qh + gi);
        *(uint4*)&sm[5120 + row * ALD + c8] = *(const uint4*)(g_Ql + gi);
    }
    __syncthreads();
    uint32_t qh[2][4], ql[2][4];
    #pragma unroll
    for (int kb = 0; kb < 2; ++kb) {
        int row = wid * 16 + (g & 1) * 8 + r;
        int hw  = kb * 16 + (g >> 1) * 8;
        uint32_t off = (uint32_t)(row * ALD + hw) * 2;
        ldsm4(QHI + off, qh[kb][0], qh[kb][1], qh[kb][2], qh[kb][3]);
        ldsm4(QLO + off, ql[kb][0], ql[kb][1], ql[kb][2], ql[kb][3]);
    }

    float o[4][4];
    #pragma unroll
    for (int i = 0; i < 4; i++)
        #pragma unroll
        for (int j = 0; j < 4; j++) o[i][j] = 0.f;
    float m0 = -INFINITY, m1 = -INFINITY, l0 = 0.f, l1 = 0.f;

    const size_t kvbase = (size_t)bh * S_ * D_;
    const int row_ld = tid >> 2, c8_ld = (tid & 3) * 8;

    // preload tile 0
    uint4 rkh, rkl, rvh, rvl;
    {
        size_t gi = kvbase + (size_t)row_ld * D_ + c8_ld;
        rkh = *(const uint4*)(g_Kh + gi);
        rkl = *(const uint4*)(g_Kl + gi);
        rvh = *(const uint4*)(g_Vh + gi);
        rvl = *(const uint4*)(g_Vl + gi);
    }

    for (int s0 = 0; s0 < S_; s0 += 64) {
        __syncthreads();   // prior tile's smem reads (or Q ldsm) complete
        *(uint4*)&sm[row_ld * ALD + c8_ld]        = rkh;
        *(uint4*)&sm[2560 + row_ld * ALD + c8_ld] = rkl;
        *(uint4*)&sm[5120 + row_ld * ALD + c8_ld] = rvh;
        *(uint4*)&sm[7680 + row_ld * ALD + c8_ld] = rvl;
        __syncthreads();

        // prefetch next tile (hidden under MMA phase)
        if (s0 + 64 < S_) {
            size_t gi = kvbase + (size_t)(s0 + 64 + row_ld) * D_ + c8_ld;
            rkh = *(const uint4*)(g_Kh + gi);
            rkl = *(const uint4*)(g_Kl + gi);
            rvh = *(const uint4*)(g_Vh + gi);
            rvl = *(const uint4*)(g_Vl + gi);
        }

        // ---- S = Q K^T ----
        float s[8][4];
        #pragma unroll
        for (int j = 0; j < 8; j++)
            #pragma unroll
            for (int k = 0; k < 4; k++) s[j][k] = 0.f;

        #pragma unroll
        for (int kb = 0; kb < 2; ++kb) {
            #pragma unroll
            for (int nb = 0; nb < 4; ++nb) {
                int row = nb * 16 + (g >> 1) * 8 + r;    // s index
                int hw  = kb * 16 + (g & 1) * 8;         // d index
                uint32_t off = (uint32_t)(row * ALD + hw) * 2;
                uint32_t kh[4], kl[4];
                ldsm4(KHI + off, kh[0], kh[1], kh[2], kh[3]);
                ldsm4(KLO + off, kl[0], kl[1], kl[2], kl[3]);
                mmabf(s[nb * 2],     qh[kb], kh[0], kh[1]);
                mmabf(s[nb * 2 + 1], qh[kb], kh[2], kh[3]);
                mmabf(s[nb * 2],     qh[kb], kl[0], kl[1]);
                mmabf(s[nb * 2 + 1], qh[kb], kl[2], kl[3]);
                mmabf(s[nb * 2],     ql[kb], kh[0], kh[1]);
                mmabf(s[nb * 2 + 1], ql[kb], kh[2], kh[3]);
            }
        }

        // ---- online softmax (base-2 domain) ----
        float mx0 = m0, mx1 = m1;
        #pragma unroll
        for (int j = 0; j < 8; ++j) {
            mx0 = fmaxf(mx0, fmaxf(s[j][0], s[j][1]));
            mx1 = fmaxf(mx1, fmaxf(s[j][2], s[j][3]));
        }
        mx0 = fmaxf(mx0, __shfl_xor_sync(0xffffffffu, mx0, 1));
        mx0 = fmaxf(mx0, __shfl_xor_sync(0xffffffffu, mx0, 2));
        mx1 = fmaxf(mx1, __shfl_xor_sync(0xffffffffu, mx1, 1));
        mx1 = fmaxf(mx1, __shfl_xor_sync(0xffffffffu, mx1, 2));
        float c0 = ex2f(m0 - mx0), c1 = ex2f(m1 - mx1);
        m0 = mx0; m1 = mx1;
        #pragma unroll
        for (int nf = 0; nf < 4; ++nf) {
            o[nf][0] *= c0; o[nf][1] *= c0; o[nf][2] *= c1; o[nf][3] *= c1;
        }

        // ---- O += P V (exp + split inlined per kb) ----
        float sum0 = 0.f, sum1 = 0.f;
        #pragma unroll
        for (int kb = 0; kb < 4; ++kb) {
            uint32_t aH[4], aL[4];
            #pragma unroll
            for (int jj = 0; jj < 2; ++jj) {
                int j = 2 * kb + jj;
                float p0 = ex2f(s[j][0] - m0);
                float p1 = ex2f(s[j][1] - m0);
                float p2 = ex2f(s[j][2] - m1);
                float p3 = ex2f(s[j][3] - m1);
                sum0 += p0 + p1; sum1 += p2 + p3;
                split2(p0, p1, aH[jj * 2],     aL[jj * 2]);
                split2(p2, p3, aH[jj * 2 + 1], aL[jj * 2 + 1]);
            }
            #pragma unroll
            for (int nb = 0; nb < 2; ++nb) {
                int row = kb * 16 + (g & 1) * 8 + r;     // s index (k of PV)
                int hw  = nb * 16 + (g >> 1) * 8;        // d index (n of PV)
                uint32_t off = (uint32_t)(row * ALD + hw) * 2;
                uint32_t vh[4], vl[4];
                ldsm4t(VHI + off, vh[0], vh[1], vh[2], vh[3]);
                ldsm4t(VLO + off, vl[0], vl[1], vl[2], vl[3]);
                mmabf(o[nb * 2],     aH, vh[0], vh[1]);
                mmabf(o[nb * 2 + 1], aH, vh[2], vh[3]);
                mmabf(o[nb * 2],     aH, vl[0], vl[1]);
                mmabf(o[nb * 2 + 1], aH, vl[2], vl[3]);
                mmabf(o[nb * 2],     aL, vh[0], vh[1]);
                mmabf(o[nb * 2 + 1], aL, vh[2], vh[3]);
            }
        }
        sum0 += __shfl_xor_sync(0xffffffffu, sum0, 1);
        sum0 += __shfl_xor_sync(0xffffffffu, sum0, 2);
        sum1 += __shfl_xor_sync(0xffffffffu, sum1, 1);
        sum1 += __shfl_xor_sync(0xffffffffu, sum1, 2);
        l0 = l0 * c0 + sum0;
        l1 = l1 * c1 + sum1;
    }

    // ---- finalize: split to bf16 hi/lo and store into AO [B,T,C] ----
    float i0 = 1.f / l0, i1 = 1.f / l1;
    int row = t0 + wid * 16 + tq;
    #pragma unroll
    for (int nf = 0; nf < 4; ++nf) {
        int col = hidx * 32 + nf * 8 + tc * 2;
        size_t gi0 = ((size_t)(bidx * T_ + row)) * C_ + col;
        size_t gi1 = ((size_t)(bidx * T_ + row + 8)) * C_ + col;
        uint32_t h, l;
        split2(o[nf][0] * i0, o[nf][1] * i0, h, l);
        *(uint32_t*)&g_AOh[gi0] = h; *(uint32_t*)&g_AOl[gi0] = l;
        split2(o[nf][2] * i1, o[nf][3] * i1, h, l);
        *(uint32_t*)&g_AOh[gi1] = h; *(uint32_t*)&g_AOl[gi1] = l;
    }
}

// ===========================================================================
// Launch
// ===========================================================================
extern "C" void kernel_launch(void* const* d_in, const int* in_sizes, int n_in,
                              void* d_out, int out_size)
{
    const float* x   = (const float*)d_in[0];
    const float* ctx = (const float*)d_in[1];
    const float* Wq  = (const float*)d_in[2];
    const float* bq  = (const float*)d_in[3];
    const float* Wk  = (const float*)d_in[4];
    const float* bk  = (const float*)d_in[5];
    const float* Wv  = (const float*)d_in[6];
    const float* bv  = (const float*)d_in[7];
    const float* Wo  = (const float*)d_in[8];
    const float* bo  = (const float*)d_in[9];
    float* out = (float*)d_out;

    dim3 convGrid((unsigned)(NX / 4 / 256), 6);   // (4096, 6)
    conv_kernel<<<convGrid, 256>>>(x, ctx, Wq, Wk, Wv, Wo);

    dim3 qkvGrid(C_ / 64, (B_ * T_) / 128, 3);    // (8, 64, 3)
    gemm_qkv_kernel<<<qkvGrid, 256>>>(bq, bk, bv);

    dim3 attnGrid(T_ / 128, B_ * H_);             // (16, 64)
    attn_mma_kernel<<<attnGrid, 256>>>();

    dim3 gemmGrid(C_ / 64, (B_ * T_) / 128);      // (8, 64)
    gemm_out_kernel<<<gemmGrid, 256>>>(bo, out);
}

// round 6
// speedup vs baseline: 1.0131x; 1.0131x over previous
#include <cuda_runtime.h>
#include <cuda_bf16.h>
#include <math.h>
#include <stdint.h>

// Problem constants
#define B_  4
#define T_  2048
#define S_  2048
#define C_  512
#define H_  16
#define D_  32

#define NX  ((size_t)B_*T_*C_)   // 4194304
#define NW  ((size_t)C_*C_)      // 262144

// bf16 hi/lo scratch (device globals; no allocations allowed)
__device__ uint16_t g_xh[NX],  g_xl[NX];
__device__ uint16_t g_ch[NX],  g_cl[NX];
__device__ uint16_t g_wqh[NW], g_wql[NW];
__device__ uint16_t g_wkh[NW], g_wkl[NW];
__device__ uint16_t g_wvh[NW], g_wvl[NW];
__device__ uint16_t g_woh[NW], g_wol[NW];
__device__ uint16_t g_Qh[NX],  g_Ql[NX];   // [B,H,T,D] (pre-scaled)
__device__ uint16_t g_Kh[NX],  g_Kl[NX];   // [B,H,S,D]
__device__ uint16_t g_Vh[NX],  g_Vl[NX];   // [B,H,S,D]
__device__ uint16_t g_AOh[NX], g_AOl[NX];  // [B,T,C]

// ===========================================================================
// Helpers (compute_103-base-safe PTX)
// ===========================================================================
__device__ __forceinline__ uint32_t smem_u32(const void* p) {
    uint32_t a;
    asm("{ .reg .u64 t; cvta.to.shared.u64 t, %1; cvt.u32.u64 %0, t; }"
        : "=r"(a) : "l"(p));
    return a;
}
__device__ __forceinline__ void ldsm4(uint32_t addr, uint32_t& r0, uint32_t& r1,
                                      uint32_t& r2, uint32_t& r3) {
    asm volatile("ldmatrix.sync.aligned.m8n8.x4.shared.b16 {%0,%1,%2,%3}, [%4];"
                 : "=r"(r0), "=r"(r1), "=r"(r2), "=r"(r3) : "r"(addr));
}
__device__ __forceinline__ void ldsm4t(uint32_t addr, uint32_t& r0, uint32_t& r1,
                                       uint32_t& r2, uint32_t& r3) {
    asm volatile("ldmatrix.sync.aligned.m8n8.x4.trans.shared.b16 {%0,%1,%2,%3}, [%4];"
                 : "=r"(r0), "=r"(r1), "=r"(r2), "=r"(r3) : "r"(addr));
}
__device__ __forceinline__ void mmabf(float* d, const uint32_t* a,
                                      uint32_t b0, uint32_t b1) {
    asm volatile("mma.sync.aligned.m16n8k16.row.col.f32.bf16.bf16.f32 "
                 "{%0,%1,%2,%3}, {%4,%5,%6,%7}, {%8,%9}, {%0,%1,%2,%3};"
                 : "+f"(d[0]), "+f"(d[1]), "+f"(d[2]), "+f"(d[3])
                 : "r"(a[0]), "r"(a[1]), "r"(a[2]), "r"(a[3]),
                   "r"(b0), "r"(b1));
}
__device__ __forceinline__ uint32_t bfpack(float x0, float x1) {
    __nv_bfloat162 t = __floats2bfloat162_rn(x0, x1);
    return *reinterpret_cast<uint32_t*>(&t);
}
__device__ __forceinline__ void split2(float x0, float x1, uint32_t& hi, uint32_t& lo) {
    float h0 = __bfloat162float(__float2bfloat16(x0));
    float h1 = __bfloat162float(__float2bfloat16(x1));
    hi = bfpack(x0, x1);
    lo = bfpack(x0 - h0, x1 - h1);
}
__device__ __forceinline__ float ex2f(float x) {
    float y; asm("ex2.approx.ftz.f32 %0, %1;" : "=f"(y) : "f"(x)); return y;
}

// ===========================================================================
// Conversion prepass: fp32 -> (hi, lo) bf16 arrays, once per element.
// ===========================================================================
__global__ __launch_bounds__(256)
void conv_kernel(const float* __restrict__ x, const float* __restrict__ ctx,
                 const float* __restrict__ Wq, const float* __restrict__ Wk,
                 const float* __restrict__ Wv, const float* __restrict__ Wo)
{
    const int z = blockIdx.y;
    const float* src; uint16_t* dh; uint16_t* dl; size_t n;
    switch (z) {
        case 0:  src = x;   dh = g_xh;  dl = g_xl;  n = NX; break;
        case 1:  src = ctx; dh = g_ch;  dl = g_cl;  n = NX; break;
        case 2:  src = Wq;  dh = g_wqh; dl = g_wql; n = NW; break;
        case 3:  src = Wk;  dh = g_wkh; dl = g_wkl; n = NW; break;
        case 4:  src = Wv;  dh = g_wvh; dl = g_wvl; n = NW; break;
        default: src = Wo;  dh = g_woh; dl = g_wol; n = NW; break;
    }
    size_t id = (size_t)blockIdx.x * 256 + threadIdx.x;
    if (id * 4 >= n) return;
    float4 v = *(const float4*)(src + id * 4);
    uint32_t h0, l0, h1, l1;
    split2(v.x, v.y, h0, l0);
    split2(v.z, v.w, h1, l1);
    *(uint2*)(dh + id * 4) = make_uint2(h0, h1);
    *(uint2*)(dl + id * 4) = make_uint2(l0, l1);
}

// ===========================================================================
// GEMM (bf16 hi/lo in), double-buffered smem, one sync per K-chunk.
// CTA 128x64, 8 warps (4m x 2n), warp tile 32x32, K-chunk 32, 16 chunks.
// MODE=1: write (hi,lo) bf16 into [B,H,T,D]; MODE=0: fp32 [M,512].
// ===========================================================================
#define GLDA 40
#define GLDB 72
// u16 offsets within a stage
#define G_AH  0
#define G_AL  5120
#define G_BH  10240
#define G_BL  12544
#define G_STAGE 14848            // u16 per stage
#define G_SMEM  (2 * G_STAGE * 2)  // bytes = 59392

template<int MODE>
__device__ __forceinline__
void gemm_body(const uint16_t* __restrict__ Ah, const uint16_t* __restrict__ Al,
               const uint16_t* __restrict__ Bh, const uint16_t* __restrict__ Bl,
               const float* __restrict__ bias, float* __restrict__ Cf,
               uint16_t* __restrict__ Ch, uint16_t* __restrict__ Cl,
               float outscale, int bm, int bn)
{
    extern __shared__ uint16_t sg[];

    const int tid = threadIdx.x;
    const int lane = tid & 31, wid = tid >> 5;
    const int g = lane >> 3, r = lane & 7;
    const int tq = lane >> 2, tc = lane & 3;
    const int wm = wid >> 1, wn = wid & 1;

    const int rowA = tid >> 2,  c8A = (tid & 3) * 8;   // +64 rows for i=1
    const int rowB = tid >> 3,  n8B = (tid & 7) * 8;

    float acc[2][4][4];
    #pragma unroll
    for (int i = 0; i < 2; i++)
        #pragma unroll
        for (int j = 0; j < 4; j++)
            #pragma unroll
            for (int k = 0; k < 4; k++) acc[i][j][k] = 0.f;

    uint4 rah[2], ral[2], rbh, rbl;

    auto ldg_chunk = [&](int c) {
        #pragma unroll
        for (int i = 0; i < 2; ++i) {
            size_t gi = (size_t)(bm + i * 64 + rowA) * 512 + c * 32 + c8A;
            rah[i] = *(const uint4*)(Ah + gi);
            ral[i] = *(const uint4*)(Al + gi);
        }
        size_t gb = (size_t)(c * 32 + rowB) * 512 + bn + n8B;
        rbh = *(const uint4*)(Bh + gb);
        rbl = *(const uint4*)(Bl + gb);
    };
    auto sts_chunk = [&](int p) {
        uint16_t* st = sg + p * G_STAGE;
        #pragma unroll
        for (int i = 0; i < 2; ++i) {
            int row = i * 64 + rowA;
            *(uint4*)&st[G_AH + row * GLDA + c8A] = rah[i];
            *(uint4*)&st[G_AL + row * GLDA + c8A] = ral[i];
        }
        *(uint4*)&st[G_BH + rowB * GLDB + n8B] = rbh;
        *(uint4*)&st[G_BL + rowB * GLDB + n8B] = rbl;
    };

    const uint32_t sb = smem_u32(sg);

    ldg_chunk(0);
    sts_chunk(0);
    __syncthreads();
    ldg_chunk(1);

    for (int c = 0; c < 16; ++c) {
        const int p = c & 1;
        const uint32_t stb = sb + (uint32_t)p * (G_STAGE * 2);

        #pragma unroll
        for (int kb = 0; kb < 2; ++kb) {
            uint32_t ah[2][4], al[2][4];
            #pragma unroll
            for (int mf = 0; mf < 2; ++mf) {
                int row = wm * 32 + mf * 16 + (g & 1) * 8 + r;
                int hw  = kb * 16 + (g >> 1) * 8;
                uint32_t off = (uint32_t)(row * GLDA + hw) * 2;
                ldsm4(stb + G_AH * 2 + off, ah[mf][0], ah[mf][1], ah[mf][2], ah[mf][3]);
                ldsm4(stb + G_AL * 2 + off, al[mf][0], al[mf][1], al[mf][2], al[mf][3]);
            }
            #pragma unroll
            for (int nb = 0; nb < 2; ++nb) {
                int krow = kb * 16 + (g & 1) * 8 + r;
                int hw   = wn * 32 + nb * 16 + (g >> 1) * 8;
                uint32_t off = (uint32_t)(krow * GLDB + hw) * 2;
                uint32_t bh[4], bl[4];
                ldsm4t(stb + G_BH * 2 + off, bh[0], bh[1], bh[2], bh[3]);
                ldsm4t(stb + G_BL * 2 + off, bl[0], bl[1], bl[2], bl[3]);
                #pragma unroll
                for (int mf = 0; mf < 2; ++mf) {
                    #pragma unroll
                    for (int h2 = 0; h2 < 2; ++h2) {
                        float* d = acc[mf][nb * 2 + h2];
                        mmabf(d, ah[mf], bh[h2 * 2], bh[h2 * 2 + 1]);
                        mmabf(d, ah[mf], bl[h2 * 2], bl[h2 * 2 + 1]);
                        mmabf(d, al[mf], bh[h2 * 2], bh[h2 * 2 + 1]);
                    }
                }
            }
        }

        if (c < 15) {
            sts_chunk(p ^ 1);
            if (c < 14) ldg_chunk(c + 2);
            __syncthreads();
        }
    }

    #pragma unroll
    for (int mf = 0; mf < 2; ++mf) {
        int row0 = bm + wm * 32 + mf * 16 + tq;
        #pragma unroll
        for (int nf = 0; nf < 4; ++nf) {
            int col = bn + wn * 32 + nf * 8 + tc * 2;
            float b0v = bias[col], b1v = bias[col + 1];
            float v00 = (acc[mf][nf][0] + b0v) * outscale;
            float v01 = (acc[mf][nf][1] + b1v) * outscale;
            float v10 = (acc[mf][nf][2] + b0v) * outscale;
            float v11 = (acc[mf][nf][3] + b1v) * outscale;
            if (MODE == 1) {
                int bb = row0 >> 11, t = row0 & 2047;
                int hh = col >> 5, d = col & 31;
                size_t i0 = (((size_t)(bb * H_ + hh)) * T_ + t) * D_ + d;
                size_t i1 = (((size_t)(bb * H_ + hh)) * T_ + t + 8) * D_ + d;
                uint32_t h, l;
                split2(v00, v01, h, l);
                *(uint32_t*)&Ch[i0] = h; *(uint32_t*)&Cl[i0] = l;
                split2(v10, v11, h, l);
                *(uint32_t*)&Ch[i1] = h; *(uint32_t*)&Cl[i1] = l;
            } else {
                *(float2*)&Cf[(size_t)row0 * 512 + col] = make_float2(v00, v01);
                *(float2*)&Cf[(size_t)(row0 + 8) * 512 + col] = make_float2(v10, v11);
            }
        }
    }
}

__global__ __launch_bounds__(256)
void gemm_qkv_kernel(const float* __restrict__ bq, const float* __restrict__ bk,
                     const float* __restrict__ bv)
{
    const float SC = 0.17677669529663689f * 1.4426950408889634f; // scale*log2e
    const int z = blockIdx.z;
    const uint16_t *Ah, *Al, *Bh, *Bl;
    const float* bias;
    uint16_t *Ch, *Cl;
    float sc;
    if (z == 0) { Ah=g_xh; Al=g_xl; Bh=g_wqh; Bl=g_wql; bias=bq; Ch=g_Qh; Cl=g_Ql; sc=SC; }
    else if (z == 1) { Ah=g_ch; Al=g_cl; Bh=g_wkh; Bl=g_wkl; bias=bk; Ch=g_Kh; Cl=g_Kl; sc=1.f; }
    else { Ah=g_ch; Al=g_cl; Bh=g_wvh; Bl=g_wvl; bias=bv; Ch=g_Vh; Cl=g_Vl; sc=1.f; }
    gemm_body<1>(Ah, Al, Bh, Bl, bias, nullptr, Ch, Cl, sc,
                 blockIdx.y * 128, blockIdx.x * 64);
}

__global__ __launch_bounds__(256)
void gemm_out_kernel(const float* __restrict__ bo, float* __restrict__ out)
{
    gemm_body<0>(g_AOh, g_AOl, g_woh, g_wol, bo, out, nullptr, nullptr, 1.f,
                 blockIdx.y * 128, blockIdx.x * 64);
}

// ===========================================================================
// Flash attention, double-buffered K/V smem, one sync per S-tile.
// CTA: 128 q-rows (8 warps x 16), S-tile 64.
// ===========================================================================
#define ALD 40
// u16 offsets within a stage
#define A_KH 0
#define A_KL 2560
#define A_VH 5120
#define A_VL 7680
#define A_STAGE 10240

__global__ __launch_bounds__(256)
void attn_mma_kernel()
{
    __shared__ uint16_t sm[2 * A_STAGE];   // 40960 B

    const int tid = threadIdx.x, lane = tid & 31, wid = tid >> 5;
    const int g = lane >> 3, r = lane & 7;
    const int tq = lane >> 2, tc = lane & 3;
    const int bh = blockIdx.y, bidx = bh >> 4, hidx = bh & 15;
    const int t0 = blockIdx.x * 128;

    const uint32_t sb = smem_u32(sm);
    const size_t kvbase = (size_t)bh * S_ * D_;
    const int row_ld = tid >> 2, c8_ld = (tid & 3) * 8;   // 64 rows x 32 cols

    // staging regs
    uint4 rkh, rkl, rvh, rvl;
    auto ldg_tile = [&](int s0) {
        size_t gi = kvbase + (size_t)(s0 + row_ld) * D_ + c8_ld;
        rkh = *(const uint4*)(g_Kh + gi);
        rkl = *(const uint4*)(g_Kl + gi);
        rvh = *(const uint4*)(g_Vh + gi);
        rvl = *(const uint4*)(g_Vl + gi);
    };
    auto sts_tile = [&](int p) {
        uint16_t* st = sm + p * A_STAGE;
        *(uint4*)&st[A_KH + row_ld * ALD + c8_ld] = rkh;
        *(uint4*)&st[A_KL + row_ld * ALD + c8_ld] = rkl;
        *(uint4*)&st[A_VH + row_ld * ALD + c8_ld] = rvh;
        *(uint4*)&st[A_VL + row_ld * ALD + c8_ld] = rvl;
    };

    ldg_tile(0);   // in flight during Q setup

    // ---- Q (pre-scaled) hi/lo -> stage-0 smem -> registers ----
    #pragma unroll
    for (int i = 0; i < 2; ++i) {
        int id = i * 256 + tid, row = id >> 2, c8 = (id & 3) * 8;
        size_t gi = ((size_t)bh * T_ + t0 + row) * D_ + c8;
        *(uint4*)&sm[row * ALD + c8]        = *(const uint4*)(g_Qh + gi);
        *(uint4*)&sm[5120 + row * ALD + c8] = *(const uint4*)(g_Ql + gi);
    }
    __syncthreads();
    uint32_t qh[2][4], ql[2][4];
    #pragma unroll
    for (int kb = 0; kb < 2; ++kb) {
        int row = wid * 16 + (g & 1) * 8 + r;
        int hw  = kb * 16 + (g >> 1) * 8;
        uint32_t off = (uint32_t)(row * ALD + hw) * 2;
        ldsm4(sb + off,            qh[kb][0], qh[kb][1], qh[kb][2], qh[kb][3]);
        ldsm4(sb + 10240 + off,    ql[kb][0], ql[kb][1], ql[kb][2], ql[kb][3]);
    }
    __syncthreads();      // all warps done reading Q region

    sts_tile(0);
    __syncthreads();
    ldg_tile(64);

    float o[4][4];
    #pragma unroll
    for (int i = 0; i < 4; i++)
        #pragma unroll
        for (int j = 0; j < 4; j++) o[i][j] = 0.f;
    float m0 = -INFINITY, m1 = -INFINITY, l0 = 0.f, l1 = 0.f;

    for (int it = 0; it < S_ / 64; ++it) {
        const int p = it & 1;
        const uint32_t stb = sb + (uint32_t)p * (A_STAGE * 2);

        // ---- S = Q K^T ----
        float s[8][4];
        #pragma unroll
        for (int j = 0; j < 8; j++)
            #pragma unroll
            for (int k = 0; k < 4; k++) s[j][k] = 0.f;

        #pragma unroll
        for (int kb = 0; kb < 2; ++kb) {
            #pragma unroll
            for (int nb = 0; nb < 4; ++nb) {
                int row = nb * 16 + (g >> 1) * 8 + r;
                int hw  = kb * 16 + (g & 1) * 8;
                uint32_t off = (uint32_t)(row * ALD + hw) * 2;
                uint32_t kh[4], kl[4];
                ldsm4(stb + A_KH * 2 + off, kh[0], kh[1], kh[2], kh[3]);
                ldsm4(stb + A_KL * 2 + off, kl[0], kl[1], kl[2], kl[3]);
                mmabf(s[nb * 2],     qh[kb], kh[0], kh[1]);
                mmabf(s[nb * 2 + 1], qh[kb], kh[2], kh[3]);
                mmabf(s[nb * 2],     qh[kb], kl[0], kl[1]);
                mmabf(s[nb * 2 + 1], qh[kb], kl[2], kl[3]);
                mmabf(s[nb * 2],     ql[kb], kh[0], kh[1]);
                mmabf(s[nb * 2 + 1], ql[kb], kh[2], kh[3]);
            }
        }

        // ---- online softmax (base-2 domain) ----
        float mx0 = m0, mx1 = m1;
        #pragma unroll
        for (int j = 0; j < 8; ++j) {
            mx0 = fmaxf(mx0, fmaxf(s[j][0], s[j][1]));
            mx1 = fmaxf(mx1, fmaxf(s[j][2], s[j][3]));
        }
        mx0 = fmaxf(mx0, __shfl_xor_sync(0xffffffffu, mx0, 1));
        mx0 = fmaxf(mx0, __shfl_xor_sync(0xffffffffu, mx0, 2));
        mx1 = fmaxf(mx1, __shfl_xor_sync(0xffffffffu, mx1, 1));
        mx1 = fmaxf(mx1, __shfl_xor_sync(0xffffffffu, mx1, 2));
        float c0 = ex2f(m0 - mx0), c1 = ex2f(m1 - mx1);
        m0 = mx0; m1 = mx1;
        #pragma unroll
        for (int nf = 0; nf < 4; ++nf) {
            o[nf][0] *= c0; o[nf][1] *= c0; o[nf][2] *= c1; o[nf][3] *= c1;
        }

        // ---- O += P V (exp + split inlined per kb) ----
        float sum0 = 0.f, sum1 = 0.f;
        #pragma unroll
        for (int kb = 0; kb < 4; ++kb) {
            uint32_t aH[4], aL[4];
            #pragma unroll
            for (int jj = 0; jj < 2; ++jj) {
                int j = 2 * kb + jj;
                float p0 = ex2f(s[j][0] - m0);
                float p1 = ex2f(s[j][1] - m0);
                float p2 = ex2f(s[j][2] - m1);
                float p3 = ex2f(s[j][3] - m1);
                sum0 += p0 + p1; sum1 += p2 + p3;
                split2(p0, p1, aH[jj * 2],     aL[jj * 2]);
                split2(p2, p3, aH[jj * 2 + 1], aL[jj * 2 + 1]);
            }
            #pragma unroll
            for (int nb = 0; nb < 2; ++nb) {
                int row = kb * 16 + (g & 1) * 8 + r;
                int hw  = nb * 16 + (g >> 1) * 8;
                uint32_t off = (uint32_t)(row * ALD + hw) * 2;
                uint32_t vh[4], vl[4];
                ldsm4t(stb + A_VH * 2 + off, vh[0], vh[1], vh[2], vh[3]);
                ldsm4t(stb + A_VL * 2 + off, vl[0], vl[1], vl[2], vl[3]);
                mmabf(o[nb * 2],     aH, vh[0], vh[1]);
                mmabf(o[nb * 2 + 1], aH, vh[2], vh[3]);
                mmabf(o[nb * 2],     aH, vl[0], vl[1]);
                mmabf(o[nb * 2 + 1], aH, vl[2], vl[3]);
                mmabf(o[nb * 2],     aL, vh[0], vh[1]);
                mmabf(o[nb * 2 + 1], aL, vh[2], vh[3]);
            }
        }
        sum0 += __shfl_xor_sync(0xffffffffu, sum0, 1);
        sum0 += __shfl_xor_sync(0xffffffffu, sum0, 2);
        sum1 += __shfl_xor_sync(0xffffffffu, sum1, 1);
        sum1 += __shfl_xor_sync(0xffffffffu, sum1, 2);
        l0 = l0 * c0 + sum0;
        l1 = l1 * c1 + sum1;

        // ---- stage next tile ----
        if (it < S_ / 64 - 1) {
            sts_tile(p ^ 1);
            if (it < S_ / 64 - 2) ldg_tile((it + 2) * 64);
            __syncthreads();
        }
    }

    // ---- finalize: split to bf16 hi/lo and store into AO [B,T,C] ----
    float i0 = 1.f / l0, i1 = 1.f / l1;
    int row = t0 + wid * 16 + tq;
    #pragma unroll
    for (int nf = 0; nf < 4; ++nf) {
        int col = hidx * 32 + nf * 8 + tc * 2;
        size_t gi0 = ((size_t)(bidx * T_ + row)) * C_ + col;
        size_t gi1 = ((size_t)(bidx * T_ + row + 8)) * C_ + col;
        uint32_t h, l;
        split2(o[nf][0] * i0, o[nf][1] * i0, h, l);
        *(uint32_t*)&g_AOh[gi0] = h; *(uint32_t*)&g_AOl[gi0] = l;
        split2(o[nf][2] * i1, o[nf][3] * i1, h, l);
        *(uint32_t*)&g_AOh[gi1] = h; *(uint32_t*)&g_AOl[gi1] = l;
    }
}

// ===========================================================================
// Launch
// ===========================================================================
extern "C" void kernel_launch(void* const* d_in, const int* in_sizes, int n_in,
                              void* d_out, int out_size)
{
    const float* x   = (const float*)d_in[0];
    const float* ctx = (const float*)d_in[1];
    const float* Wq  = (const float*)d_in[2];
    const float* bq  = (const float*)d_in[3];
    const float* Wk  = (const float*)d_in[4];
    const float* bk  = (const float*)d_in[5];
    const float* Wv  = (const float*)d_in[6];
    const float* bv  = (const float*)d_in[7];
    const float* Wo  = (const float*)d_in[8];
    const float* bo  = (const float*)d_in[9];
    float* out = (float*)d_out;

    cudaFuncSetAttribute(gemm_qkv_kernel,
                         cudaFuncAttributeMaxDynamicSharedMemorySize, G_SMEM);
    cudaFuncSetAttribute(gemm_out_kernel,
                         cudaFuncAttributeMaxDynamicSharedMemorySize, G_SMEM);

    dim3 convGrid((unsigned)(NX / 4 / 256), 6);   // (4096, 6)
    conv_kernel<<<convGrid, 256>>>(x, ctx, Wq, Wk, Wv, Wo);

    dim3 qkvGrid(C_ / 64, (B_ * T_) / 128, 3);    // (8, 64, 3)
    gemm_qkv_kernel<<<qkvGrid, 256, G_SMEM>>>(bq, bk, bv);

    dim3 attnGrid(T_ / 128, B_ * H_);             // (16, 64)
    attn_mma_kernel<<<attnGrid, 256>>>();

    dim3 gemmGrid(C_ / 64, (B_ * T_) / 128);      // (8, 64)
    gemm_out_kernel<<<gemmGrid, 256, G_SMEM>>>(bo, out);
}

// round 7
// speedup vs baseline: 1.0302x; 1.0169x over previous
#include <cuda_runtime.h>
#include <cuda_bf16.h>
#include <math.h>
#include <stdint.h>

// Problem constants
#define B_  4
#define T_  2048
#define S_  2048
#define C_  512
#define H_  16
#define D_  32

#define NX  ((size_t)B_*T_*C_)   // 4194304
#define NW  ((size_t)C_*C_)      // 262144

// bf16 hi/lo scratch (device globals; no allocations allowed)
__device__ uint16_t g_xh[NX],  g_xl[NX];
__device__ uint16_t g_ch[NX],  g_cl[NX];
__device__ uint16_t g_wqh[NW], g_wql[NW];
__device__ uint16_t g_wkh[NW], g_wkl[NW];
__device__ uint16_t g_wvh[NW], g_wvl[NW];
__device__ uint16_t g_woh[NW], g_wol[NW];
__device__ uint16_t g_Qh[NX],  g_Ql[NX];   // [B,H,T,D] (pre-scaled)
__device__ uint16_t g_Kh[NX],  g_Kl[NX];   // [B,H,S,D]
__device__ uint16_t g_Vh[NX],  g_Vl[NX];   // [B,H,S,D]
__device__ uint16_t g_AOh[NX], g_AOl[NX];  // [B,T,C]

// ===========================================================================
// Helpers (compute_103-base-safe PTX)
// ===========================================================================
__device__ __forceinline__ uint32_t smem_u32(const void* p) {
    uint32_t a;
    asm("{ .reg .u64 t; cvta.to.shared.u64 t, %1; cvt.u32.u64 %0, t; }"
        : "=r"(a) : "l"(p));
    return a;
}
__device__ __forceinline__ void ldsm4(uint32_t addr, uint32_t& r0, uint32_t& r1,
                                      uint32_t& r2, uint32_t& r3) {
    asm volatile("ldmatrix.sync.aligned.m8n8.x4.shared.b16 {%0,%1,%2,%3}, [%4];"
                 : "=r"(r0), "=r"(r1), "=r"(r2), "=r"(r3) : "r"(addr));
}
__device__ __forceinline__ void ldsm4t(uint32_t addr, uint32_t& r0, uint32_t& r1,
                                       uint32_t& r2, uint32_t& r3) {
    asm volatile("ldmatrix.sync.aligned.m8n8.x4.trans.shared.b16 {%0,%1,%2,%3}, [%4];"
                 : "=r"(r0), "=r"(r1), "=r"(r2), "=r"(r3) : "r"(addr));
}
__device__ __forceinline__ void mmabf(float* d, const uint32_t* a,
                                      uint32_t b0, uint32_t b1) {
    asm volatile("mma.sync.aligned.m16n8k16.row.col.f32.bf16.bf16.f32 "
                 "{%0,%1,%2,%3}, {%4,%5,%6,%7}, {%8,%9}, {%0,%1,%2,%3};"
                 : "+f"(d[0]), "+f"(d[1]), "+f"(d[2]), "+f"(d[3])
                 : "r"(a[0]), "r"(a[1]), "r"(a[2]), "r"(a[3]),
                   "r"(b0), "r"(b1));
}
__device__ __forceinline__ uint32_t bfpack(float x0, float x1) {
    __nv_bfloat162 t = __floats2bfloat162_rn(x0, x1);
    return *reinterpret_cast<uint32_t*>(&t);
}
__device__ __forceinline__ void split2(float x0, float x1, uint32_t& hi, uint32_t& lo) {
    float h0 = __bfloat162float(__float2bfloat16(x0));
    float h1 = __bfloat162float(__float2bfloat16(x1));
    hi = bfpack(x0, x1);
    lo = bfpack(x0 - h0, x1 - h1);
}
__device__ __forceinline__ float ex2f(float x) {
    float y; asm("ex2.approx.ftz.f32 %0, %1;" : "=f"(y) : "f"(x)); return y;
}
// cp.async: gmem -> smem, 16 bytes, bypasses the register file
__device__ __forceinline__ void cpa16(uint32_t dst, const void* src) {
    asm volatile("cp.async.ca.shared.global [%0], [%1], 16;"
                 :: "r"(dst), "l"(src) : "memory");
}
#define CP_COMMIT() asm volatile("cp.async.commit_group;" ::: "memory")
template<int N> __device__ __forceinline__ void cp_wait() {
    asm volatile("cp.async.wait_group %0;" :: "n"(N) : "memory");
}

// ===========================================================================
// Conversion prepass: fp32 -> (hi, lo) bf16 arrays, once per element.
// ===========================================================================
__global__ __launch_bounds__(256)
void conv_kernel(const float* __restrict__ x, const float* __restrict__ ctx,
                 const float* __restrict__ Wq, const float* __restrict__ Wk,
                 const float* __restrict__ Wv, const float* __restrict__ Wo)
{
    const int z = blockIdx.y;
    const float* src; uint16_t* dh; uint16_t* dl; size_t n;
    switch (z) {
        case 0:  src = x;   dh = g_xh;  dl = g_xl;  n = NX; break;
        case 1:  src = ctx; dh = g_ch;  dl = g_cl;  n = NX; break;
        case 2:  src = Wq;  dh = g_wqh; dl = g_wql; n = NW; break;
        case 3:  src = Wk;  dh = g_wkh; dl = g_wkl; n = NW; break;
        case 4:  src = Wv;  dh = g_wvh; dl = g_wvl; n = NW; break;
        default: src = Wo;  dh = g_woh; dl = g_wol; n = NW; break;
    }
    size_t id = (size_t)blockIdx.x * 256 + threadIdx.x;
    if (id * 4 >= n) return;
    float4 v = *(const float4*)(src + id * 4);
    uint32_t h0, l0, h1, l1;
    split2(v.x, v.y, h0, l0);
    split2(v.z, v.w, h1, l1);
    *(uint2*)(dh + id * 4) = make_uint2(h0, h1);
    *(uint2*)(dl + id * 4) = make_uint2(l0, l1);
}

// ===========================================================================
// GEMM (bf16 hi/lo in), cp.async 3-stage pipeline, one sync per K-chunk.
// CTA 128x64, 8 warps (4m x 2n), warp tile 32x32, K-chunk 32, 16 chunks.
// MODE=1: write (hi,lo) bf16 into [B,H,T,D]; MODE=0: fp32 [M,512].
// ===========================================================================
#define GLDA 40
#define GLDB 72
#define G_AH  0
#define G_AL  5120
#define G_BH  10240
#define G_BL  12544
#define G_STAGE 14848                // u16 per stage
#define G_SMEM  (3 * G_STAGE * 2)    // 89088 bytes

template<int MODE>
__device__ __forceinline__
void gemm_body(const uint16_t* __restrict__ Ah, const uint16_t* __restrict__ Al,
               const uint16_t* __restrict__ Bh, const uint16_t* __restrict__ Bl,
               const float* __restrict__ bias, float* __restrict__ Cf,
               uint16_t* __restrict__ Ch, uint16_t* __restrict__ Cl,
               float outscale, int bm, int bn)
{
    extern __shared__ uint16_t sg[];
    const uint32_t sb = smem_u32(sg);

    const int tid = threadIdx.x;
    const int lane = tid & 31, wid = tid >> 5;
    const int g = lane >> 3, r = lane & 7;
    const int tq = lane >> 2, tc = lane & 3;
    const int wm = wid >> 1, wn = wid & 1;

    const int rowA = tid >> 2, c8A = (tid & 3) * 8;
    const int rowB = tid >> 3, n8B = (tid & 7) * 8;

    auto issue = [&](int c) {
        uint32_t st = sb + (uint32_t)(c % 3) * (G_STAGE * 2);
        #pragma unroll
        for (int i = 0; i < 2; ++i) {
            int row = i * 64 + rowA;
            size_t gi = (size_t)(bm + row) * 512 + c * 32 + c8A;
            cpa16(st + (uint32_t)(G_AH + row * GLDA + c8A) * 2, Ah + gi);
            cpa16(st + (uint32_t)(G_AL + row * GLDA + c8A) * 2, Al + gi);
        }
        size_t gb = (size_t)(c * 32 + rowB) * 512 + bn + n8B;
        cpa16(st + (uint32_t)(G_BH + rowB * GLDB + n8B) * 2, Bh + gb);
        cpa16(st + (uint32_t)(G_BL + rowB * GLDB + n8B) * 2, Bl + gb);
        CP_COMMIT();
    };

    float acc[2][4][4];
    #pragma unroll
    for (int i = 0; i < 2; i++)
        #pragma unroll
        for (int j = 0; j < 4; j++)
            #pragma unroll
            for (int k = 0; k < 4; k++) acc[i][j][k] = 0.f;

    issue(0);
    issue(1);

    for (int c = 0; c < 16; ++c) {
        if (c < 15) cp_wait<1>(); else cp_wait<0>();
        __syncthreads();
        if (c < 14) issue(c + 2);

        const uint32_t stb = sb + (uint32_t)(c % 3) * (G_STAGE * 2);

        #pragma unroll
        for (int kb = 0; kb < 2; ++kb) {
            uint32_t ah[2][4], al[2][4];
            #pragma unroll
            for (int mf = 0; mf < 2; ++mf) {
                int row = wm * 32 + mf * 16 + (g & 1) * 8 + r;
                int hw  = kb * 16 + (g >> 1) * 8;
                uint32_t off = (uint32_t)(row * GLDA + hw) * 2;
                ldsm4(stb + G_AH * 2 + off, ah[mf][0], ah[mf][1], ah[mf][2], ah[mf][3]);
                ldsm4(stb + G_AL * 2 + off, al[mf][0], al[mf][1], al[mf][2], al[mf][3]);
            }
            #pragma unroll
            for (int nb = 0; nb < 2; ++nb) {
                int krow = kb * 16 + (g & 1) * 8 + r;
                int hw   = wn * 32 + nb * 16 + (g >> 1) * 8;
                uint32_t off = (uint32_t)(krow * GLDB + hw) * 2;
                uint32_t bh[4], bl[4];
                ldsm4t(stb + G_BH * 2 + off, bh[0], bh[1], bh[2], bh[3]);
                ldsm4t(stb + G_BL * 2 + off, bl[0], bl[1], bl[2], bl[3]);
                #pragma unroll
                for (int mf = 0; mf < 2; ++mf) {
                    #pragma unroll
                    for (int h2 = 0; h2 < 2; ++h2) {
                        float* d = acc[mf][nb * 2 + h2];
                        mmabf(d, ah[mf], bh[h2 * 2], bh[h2 * 2 + 1]);
                        mmabf(d, ah[mf], bl[h2 * 2], bl[h2 * 2 + 1]);
                        mmabf(d, al[mf], bh[h2 * 2], bh[h2 * 2 + 1]);
                    }
                }
            }
        }
    }

    #pragma unroll
    for (int mf = 0; mf < 2; ++mf) {
        int row0 = bm + wm * 32 + mf * 16 + tq;
        #pragma unroll
        for (int nf = 0; nf < 4; ++nf) {
            int col = bn + wn * 32 + nf * 8 + tc * 2;
            float b0v = bias[col], b1v = bias[col + 1];
            float v00 = (acc[mf][nf][0] + b0v) * outscale;
            float v01 = (acc[mf][nf][1] + b1v) * outscale;
            float v10 = (acc[mf][nf][2] + b0v) * outscale;
            float v11 = (acc[mf][nf][3] + b1v) * outscale;
            if (MODE == 1) {
                int bb = row0 >> 11, t = row0 & 2047;
                int hh = col >> 5, d = col & 31;
                size_t i0 = (((size_t)(bb * H_ + hh)) * T_ + t) * D_ + d;
                size_t i1 = (((size_t)(bb * H_ + hh)) * T_ + t + 8) * D_ + d;
                uint32_t h, l;
                split2(v00, v01, h, l);
                *(uint32_t*)&Ch[i0] = h; *(uint32_t*)&Cl[i0] = l;
                split2(v10, v11, h, l);
                *(uint32_t*)&Ch[i1] = h; *(uint32_t*)&Cl[i1] = l;
            } else {
                *(float2*)&Cf[(size_t)row0 * 512 + col] = make_float2(v00, v01);
                *(float2*)&Cf[(size_t)(row0 + 8) * 512 + col] = make_float2(v10, v11);
            }
        }
    }
}

__global__ __launch_bounds__(256, 2)
void gemm_qkv_kernel(const float* __restrict__ bq, const float* __restrict__ bk,
                     const float* __restrict__ bv)
{
    const float SC = 0.17677669529663689f * 1.4426950408889634f; // scale*log2e
    const int z = blockIdx.z;
    const uint16_t *Ah, *Al, *Bh, *Bl;
    const float* bias;
    uint16_t *Ch, *Cl;
    float sc;
    if (z == 0) { Ah=g_xh; Al=g_xl; Bh=g_wqh; Bl=g_wql; bias=bq; Ch=g_Qh; Cl=g_Ql; sc=SC; }
    else if (z == 1) { Ah=g_ch; Al=g_cl; Bh=g_wkh; Bl=g_wkl; bias=bk; Ch=g_Kh; Cl=g_Kl; sc=1.f; }
    else { Ah=g_ch; Al=g_cl; Bh=g_wvh; Bl=g_wvl; bias=bv; Ch=g_Vh; Cl=g_Vl; sc=1.f; }
    gemm_body<1>(Ah, Al, Bh, Bl, bias, nullptr, Ch, Cl, sc,
                 blockIdx.y * 128, blockIdx.x * 64);
}

__global__ __launch_bounds__(256, 2)
void gemm_out_kernel(const float* __restrict__ bo, float* __restrict__ out)
{
    gemm_body<0>(g_AOh, g_AOl, g_woh, g_wol, bo, out, nullptr, nullptr, 1.f,
                 blockIdx.y * 128, blockIdx.x * 64);
}

// ===========================================================================
// Flash attention: 4 warps x 32 query rows (2 m-frags/warp), S-tile 64,
// cp.async 3-stage K/V pipeline. Each K/V ldsm pair feeds 12 MMAs (1:6).
// ===========================================================================
#define ALD 40
#define A_KH 0
#define A_KL 2560
#define A_VH 5120
#define A_VL 7680
#define A_STAGE 10240   // u16 per stage (20480 B); 3 stages = 61440 B

__global__ __launch_bounds__(128, 3)
void attn_mma_kernel()
{
    __shared__ uint16_t sm[3 * A_STAGE];

    const int tid = threadIdx.x, lane = tid & 31, wid = tid >> 5;   // wid 0..3
    const int g = lane >> 3, r = lane & 7;
    const int tq = lane >> 2, tc = lane & 3;
    const int bh = blockIdx.y, bidx = bh >> 4, hidx = bh & 15;
    const int t0 = blockIdx.x * 128;

    const uint32_t sb = smem_u32(sm);
    const size_t kvbase = (size_t)bh * S_ * D_;
    const int arow = tid >> 2, acol = (tid & 3) * 8;   // 32 rows x 4 col-groups

    // K/V tile ti (64 rows) -> stage ti%3; 8 cp.async (16B) per thread.
    auto issue_tile = [&](int ti) {
        uint32_t st = sb + (uint32_t)(ti % 3) * (A_STAGE * 2);
        #pragma unroll
        for (int i = 0; i < 2; ++i) {
            int row = i * 32 + arow;
            size_t gi = kvbase + (size_t)(ti * 64 + row) * D_ + acol;
            uint32_t o = (uint32_t)(row * ALD + acol) * 2;
            cpa16(st + A_KH * 2 + o, g_Kh + gi);
            cpa16(st + A_KL * 2 + o, g_Kl + gi);
            cpa16(st + A_VH * 2 + o, g_Vh + gi);
            cpa16(st + A_VL * 2 + o, g_Vl + gi);
        }
        CP_COMMIT();
    };

    // ---- prologue: Q (group 0) + tiles 0,1 (groups 1,2) ----
    {
        uint32_t qst = sb + 2u * (A_STAGE * 2);   // stage 2 doubles as Q staging
        #pragma unroll
        for (int i = 0; i < 4; ++i) {
            int row = i * 32 + arow;
            size_t gi = ((size_t)bh * T_ + t0 + row) * D_ + acol;
            cpa16(qst + (uint32_t)(row * ALD + acol) * 2, g_Qh + gi);
            cpa16(qst + (uint32_t)(5120 + row * ALD + acol) * 2, g_Ql + gi);
        }
        CP_COMMIT();
    }
    issue_tile(0);
    issue_tile(1);

    cp_wait<2>();          // Q staged (tiles 0,1 may still be in flight)
    __syncthreads();

    uint32_t qh[2][2][4], ql[2][2][4];   // [mf][kb][frag]
    {
        uint32_t qhb = sb + 2u * (A_STAGE * 2);
        #pragma unroll
        for (int mf = 0; mf < 2; ++mf) {
            #pragma unroll
            for (int kb = 0; kb < 2; ++kb) {
                int row = wid * 32 + mf * 16 + (g & 1) * 8 + r;
                int hw  = kb * 16 + (g >> 1) * 8;
                uint32_t off = (uint32_t)(row * ALD + hw) * 2;
                ldsm4(qhb + off, qh[mf][kb][0], qh[mf][kb][1], qh[mf][kb][2], qh[mf][kb][3]);
                ldsm4(qhb + 5120 * 2 + off, ql[mf][kb][0], ql[mf][kb][1], ql[mf][kb][2], ql[mf][kb][3]);
            }
        }
    }

    float o[2][4][4];
    #pragma unroll
    for (int mf = 0; mf < 2; mf++)
        #pragma unroll
        for (int i = 0; i < 4; i++)
            #pragma unroll
            for (int j = 0; j < 4; j++) o[mf][i][j] = 0.f;
    float m_[2][2] = {{-INFINITY, -INFINITY}, {-INFINITY, -INFINITY}};
    float l_[2][2] = {{0.f, 0.f}, {0.f, 0.f}};

    const int NT = S_ / 64;   // 32
    for (int it = 0; it < NT; ++it) {
        if (it < NT - 1) cp_wait<1>(); else cp_wait<0>();
        __syncthreads();                       // tile `it` visible; stage (it+2)%3 free
        if (it < NT - 2) issue_tile(it + 2);

        const uint32_t stb = sb + (uint32_t)(it % 3) * (A_STAGE * 2);

        // ---- S = Q K^T ----
        float s[2][8][4];
        #pragma unroll
        for (int mf = 0; mf < 2; mf++)
            #pragma unroll
            for (int j = 0; j < 8; j++)
                #pragma unroll
                for (int k = 0; k < 4; k++) s[mf][j][k] = 0.f;

        #pragma unroll
        for (int kb = 0; kb < 2; ++kb) {
            #pragma unroll
            for (int nb = 0; nb < 4; ++nb) {
                int row = nb * 16 + (g >> 1) * 8 + r;
                int hw  = kb * 16 + (g & 1) * 8;
                uint32_t off = (uint32_t)(row * ALD + hw) * 2;
                uint32_t kh[4], kl[4];
                ldsm4(stb + A_KH * 2 + off, kh[0], kh[1], kh[2], kh[3]);
                ldsm4(stb + A_KL * 2 + off, kl[0], kl[1], kl[2], kl[3]);
                #pragma unroll
                for (int mf = 0; mf < 2; ++mf) {
                    mmabf(s[mf][nb * 2],     qh[mf][kb], kh[0], kh[1]);
                    mmabf(s[mf][nb * 2 + 1], qh[mf][kb], kh[2], kh[3]);
                    mmabf(s[mf][nb * 2],     qh[mf][kb], kl[0], kl[1]);
                    mmabf(s[mf][nb * 2 + 1], qh[mf][kb], kl[2], kl[3]);
                    mmabf(s[mf][nb * 2],     ql[mf][kb], kh[0], kh[1]);
                    mmabf(s[mf][nb * 2 + 1], ql[mf][kb], kh[2], kh[3]);
                }
            }
        }

        // ---- online softmax (base-2 domain), per m-frag ----
        float c_[2][2];
        #pragma unroll
        for (int mf = 0; mf < 2; ++mf) {
            float mx0 = m_[mf][0], mx1 = m_[mf][1];
            #pragma unroll
            for (int j = 0; j < 8; ++j) {
                mx0 = fmaxf(mx0, fmaxf(s[mf][j][0], s[mf][j][1]));
                mx1 = fmaxf(mx1, fmaxf(s[mf][j][2], s[mf][j][3]));
            }
            mx0 = fmaxf(mx0, __shfl_xor_sync(0xffffffffu, mx0, 1));
            mx0 = fmaxf(mx0, __shfl_xor_sync(0xffffffffu, mx0, 2));
            mx1 = fmaxf(mx1, __shfl_xor_sync(0xffffffffu, mx1, 1));
            mx1 = fmaxf(mx1, __shfl_xor_sync(0xffffffffu, mx1, 2));
            c_[mf][0] = ex2f(m_[mf][0] - mx0);
            c_[mf][1] = ex2f(m_[mf][1] - mx1);
            m_[mf][0] = mx0; m_[mf][1] = mx1;
            #pragma unroll
            for (int nf = 0; nf < 4; ++nf) {
                o[mf][nf][0] *= c_[mf][0]; o[mf][nf][1] *= c_[mf][0];
                o[mf][nf][2] *= c_[mf][1]; o[mf][nf][3] *= c_[mf][1];
            }
        }

        // ---- O += P V (exp + split inlined per kb) ----
        float sum_[2][2] = {{0.f, 0.f}, {0.f, 0.f}};
        #pragma unroll
        for (int kb = 0; kb < 4; ++kb) {
            uint32_t aH[2][4], aL[2][4];
            #pragma unroll
            for (int mf = 0; mf < 2; ++mf) {
                #pragma unroll
                for (int jj = 0; jj < 2; ++jj) {
                    int j = 2 * kb + jj;
                    float p0 = ex2f(s[mf][j][0] - m_[mf][0]);
                    float p1 = ex2f(s[mf][j][1] - m_[mf][0]);
                    float p2 = ex2f(s[mf][j][2] - m_[mf][1]);
                    float p3 = ex2f(s[mf][j][3] - m_[mf][1]);
                    sum_[mf][0] += p0 + p1; sum_[mf][1] += p2 + p3;
                    split2(p0, p1, aH[mf][jj * 2],     aL[mf][jj * 2]);
                    split2(p2, p3, aH[mf][jj * 2 + 1], aL[mf][jj * 2 + 1]);
                }
            }
            #pragma unroll
            for (int nb = 0; nb < 2; ++nb) {
                int row = kb * 16 + (g & 1) * 8 + r;
                int hw  = nb * 16 + (g >> 1) * 8;
                uint32_t off = (uint32_t)(row * ALD + hw) * 2;
                uint32_t vh[4], vl[4];
                ldsm4t(stb + A_VH * 2 + off, vh[0], vh[1], vh[2], vh[3]);
                ldsm4t(stb + A_VL * 2 + off, vl[0], vl[1], vl[2], vl[3]);
                #pragma unroll
                for (int mf = 0; mf < 2; ++mf) {
                    mmabf(o[mf][nb * 2],     aH[mf], vh[0], vh[1]);
                    mmabf(o[mf][nb * 2 + 1], aH[mf], vh[2], vh[3]);
                    mmabf(o[mf][nb * 2],     aH[mf], vl[0], vl[1]);
                    mmabf(o[mf][nb * 2 + 1], aH[mf], vl[2], vl[3]);
                    mmabf(o[mf][nb * 2],     aL[mf], vh[0], vh[1]);
                    mmabf(o[mf][nb * 2 + 1], aL[mf], vh[2], vh[3]);
                }
            }
        }
        #pragma unroll
        for (int mf = 0; mf < 2; ++mf) {
            sum_[mf][0] += __shfl_xor_sync(0xffffffffu, sum_[mf][0], 1);
            sum_[mf][0] += __shfl_xor_sync(0xffffffffu, sum_[mf][0], 2);
            sum_[mf][1] += __shfl_xor_sync(0xffffffffu, sum_[mf][1], 1);
            sum_[mf][1] += __shfl_xor_sync(0xffffffffu, sum_[mf][1], 2);
            l_[mf][0] = l_[mf][0] * c_[mf][0] + sum_[mf][0];
            l_[mf][1] = l_[mf][1] * c_[mf][1] + sum_[mf][1];
        }
    }

    // ---- finalize: split to bf16 hi/lo and store into AO [B,T,C] ----
    #pragma unroll
    for (int mf = 0; mf < 2; ++mf) {
        float i0 = 1.f / l_[mf][0], i1 = 1.f / l_[mf][1];
        int row = t0 + wid * 32 + mf * 16 + tq;
        #pragma unroll
        for (int nf = 0; nf < 4; ++nf) {
            int col = hidx * 32 + nf * 8 + tc * 2;
            size_t gi0 = ((size_t)(bidx * T_ + row)) * C_ + col;
            size_t gi1 = ((size_t)(bidx * T_ + row + 8)) * C_ + col;
            uint32_t h, l;
            split2(o[mf][nf][0] * i0, o[mf][nf][1] * i0, h, l);
            *(uint32_t*)&g_AOh[gi0] = h; *(uint32_t*)&g_AOl[gi0] = l;
            split2(o[mf][nf][2] * i1, o[mf][nf][3] * i1, h, l);
            *(uint32_t*)&g_AOh[gi1] = h; *(uint32_t*)&g_AOl[gi1] = l;
        }
    }
}

// ===========================================================================
// Launch
// ===========================================================================
extern "C" void kernel_launch(void* const* d_in, const int* in_sizes, int n_in,
                              void* d_out, int out_size)
{
    const float* x   = (const float*)d_in[0];
    const float* ctx = (const float*)d_in[1];
    const float* Wq  = (const float*)d_in[2];
    const float* bq  = (const float*)d_in[3];
    const float* Wk  = (const float*)d_in[4];
    const float* bk  = (const float*)d_in[5];
    const float* Wv  = (const float*)d_in[6];
    const float* bv  = (const float*)d_in[7];
    const float* Wo  = (const float*)d_in[8];
    const float* bo  = (const float*)d_in[9];
    float* out = (float*)d_out;

    cudaFuncSetAttribute(gemm_qkv_kernel,
                         cudaFuncAttributeMaxDynamicSharedMemorySize, G_SMEM);
    cudaFuncSetAttribute(gemm_out_kernel,
                         cudaFuncAttributeMaxDynamicSharedMemorySize, G_SMEM);

    dim3 convGrid((unsigned)(NX / 4 / 256), 6);   // (4096, 6)
    conv_kernel<<<convGrid, 256>>>(x, ctx, Wq, Wk, Wv, Wo);

    dim3 qkvGrid(C_ / 64, (B_ * T_) / 128, 3);    // (8, 64, 3)
    gemm_qkv_kernel<<<qkvGrid, 256, G_SMEM>>>(bq, bk, bv);

    dim3 attnGrid(T_ / 128, B_ * H_);             // (16, 64)
    attn_mma_kernel<<<attnGrid, 128>>>();

    dim3 gemmGrid(C_ / 64, (B_ * T_) / 128);      // (8, 64)
    gemm_out_kernel<<<gemmGrid, 256, G_SMEM>>>(bo, out);
}